// round 4
// baseline (speedup 1.0000x reference)
#include <cuda_runtime.h>
#include <cuda_bf16.h>
#include <cstdint>

// ===================== problem constants =====================
#define NNF 128
#define NEF 64
#define NGF 64
#define HID 128
#define TGT 64
#define KDIM 384

#define THREADS 512
#define WARPS 16
#define GRID_X 152

// fragment tile counts
#define KT1 24   // 384/16 k-tiles, GEMM1
#define NT1 16   // 128/8  n-tiles, GEMM1
#define KT2 8    // 128/16 k-tiles, GEMM2
#define NT2 8    // 64/8   n-tiles, GEMM2

// ===================== smem offsets (bytes) =====================
#define S_W1H 0u        // 24*16*32*8 = 98304
#define S_W1L 98304u    // 98304
#define S_W2H 196608u   // 8*8*32*8 = 16384
#define S_W2L 212992u   // 16384
#define S_B1  229376u   // 512
#define S_B2  229888u   // 256
#define S_TOTAL 230144u

// ===================== helpers =====================
__device__ __forceinline__ uint32_t pack2(float lo, float hi) {
    // bf16x2 with 'lo' in low 16 bits (PTX: first operand -> high half)
    uint32_t r;
    asm("cvt.rn.bf16x2.f32 %0, %1, %2;" : "=r"(r) : "f"(hi), "f"(lo));
    return r;
}
__device__ __forceinline__ float bhi(float x) {
    return __bfloat162float(__float2bfloat16_rn(x));
}
__device__ __forceinline__ void split2(float2 v, uint32_t& hi, uint32_t& lo) {
    float hx = bhi(v.x), hy = bhi(v.y);
    hi = pack2(hx, hy);
    lo = pack2(v.x - hx, v.y - hy);
}
// D += A * B  (m16n8k16, bf16 in, f32 accum)
__device__ __forceinline__ void mma_bf16(float* c, const uint32_t* a, uint32_t b0, uint32_t b1) {
    asm volatile("mma.sync.aligned.m16n8k16.row.col.f32.bf16.bf16.f32 "
        "{%0,%1,%2,%3}, {%4,%5,%6,%7}, {%8,%9}, {%0,%1,%2,%3};"
        : "+f"(c[0]), "+f"(c[1]), "+f"(c[2]), "+f"(c[3])
        : "r"(a[0]), "r"(a[1]), "r"(a[2]), "r"(a[3]), "r"(b0), "r"(b1));
}

// ===================== device scratch: pre-packed B fragments (16B aligned!) =====================
__device__ __align__(16) uint2 g_w1h[KT1 * NT1 * 32];
__device__ __align__(16) uint2 g_w1l[KT1 * NT1 * 32];
__device__ __align__(16) uint2 g_w2h[KT2 * NT2 * 32];
__device__ __align__(16) uint2 g_w2l[KT2 * NT2 * 32];

// Pack W1 [384,128] and W2 [128,64] (row-major, [k][n]) into per-lane
// m16n8k16 B fragments, split into bf16 hi/lo.
// Entry ((kt*NT+nt)*32+lane): .x = {W[k0][n], W[k0+1][n]}, .y = {k0+8, k0+9},
// k0 = kt*16 + (lane&3)*2, n = nt*8 + (lane>>2).
__global__ void prep_kernel(const float* __restrict__ W1, const float* __restrict__ W2) {
    int idx = blockIdx.x * blockDim.x + threadIdx.x;
    const int total1 = KT1 * NT1 * 32;
    if (idx < total1) {
        int lane = idx & 31, tile = idx >> 5;
        int nt = tile % NT1, kt = tile / NT1;
        int k0 = kt * 16 + (lane & 3) * 2;
        int n  = nt * 8 + (lane >> 2);
        float w00 = W1[(size_t)k0 * HID + n];
        float w01 = W1[(size_t)(k0 + 1) * HID + n];
        float w10 = W1[(size_t)(k0 + 8) * HID + n];
        float w11 = W1[(size_t)(k0 + 9) * HID + n];
        float h00 = bhi(w00), h01 = bhi(w01), h10 = bhi(w10), h11 = bhi(w11);
        g_w1h[idx] = make_uint2(pack2(h00, h01), pack2(h10, h11));
        g_w1l[idx] = make_uint2(pack2(w00 - h00, w01 - h01), pack2(w10 - h10, w11 - h11));
    } else if (idx < total1 + KT2 * NT2 * 32) {
        int j = idx - total1;
        int lane = j & 31, tile = j >> 5;
        int nt = tile % NT2, kt = tile / NT2;
        int k0 = kt * 16 + (lane & 3) * 2;
        int n  = nt * 8 + (lane >> 2);
        float w00 = W2[(size_t)k0 * TGT + n];
        float w01 = W2[(size_t)(k0 + 1) * TGT + n];
        float w10 = W2[(size_t)(k0 + 8) * TGT + n];
        float w11 = W2[(size_t)(k0 + 9) * TGT + n];
        float h00 = bhi(w00), h01 = bhi(w01), h10 = bhi(w10), h11 = bhi(w11);
        g_w2h[j] = make_uint2(pack2(h00, h01), pack2(h10, h11));
        g_w2l[j] = make_uint2(pack2(w00 - h00, w01 - h01), pack2(w10 - h10, w11 - h11));
    }
}

// ===================== main fused kernel =====================
extern "C" __global__ void __launch_bounds__(THREADS, 1)
edge_mlp(const float* __restrict__ ek, const float* __restrict__ vrk,
         const float* __restrict__ vsk, const float* __restrict__ u,
         const int* __restrict__ batch,        // int32! (jax x64 disabled)
         const float* __restrict__ b1, const float* __restrict__ b2,
         float* __restrict__ out, int ngroups) {
    extern __shared__ __align__(16) unsigned char smem[];
    const int tid = threadIdx.x;

    // -------- prologue: copy packed weight fragments + biases to smem --------
    {
        uint4* d;
        const uint4* s;
        d = (uint4*)(smem + S_W1H); s = (const uint4*)g_w1h;
        for (int i = tid; i < 98304 / 16; i += THREADS) d[i] = s[i];
        d = (uint4*)(smem + S_W1L); s = (const uint4*)g_w1l;
        for (int i = tid; i < 98304 / 16; i += THREADS) d[i] = s[i];
        d = (uint4*)(smem + S_W2H); s = (const uint4*)g_w2h;
        for (int i = tid; i < 16384 / 16; i += THREADS) d[i] = s[i];
        d = (uint4*)(smem + S_W2L); s = (const uint4*)g_w2l;
        for (int i = tid; i < 16384 / 16; i += THREADS) d[i] = s[i];
        float* b1s = (float*)(smem + S_B1);
        float* b2s = (float*)(smem + S_B2);
        if (tid < HID) b1s[tid] = b1[tid];
        if (tid < TGT) b2s[tid] = b2[tid];
    }
    __syncthreads();

    const uint2* w1h = (const uint2*)(smem + S_W1H);
    const uint2* w1l = (const uint2*)(smem + S_W1L);
    const uint2* w2h = (const uint2*)(smem + S_W2H);
    const uint2* w2l = (const uint2*)(smem + S_W2L);
    const float* b1s = (const float*)(smem + S_B1);
    const float* b2s = (const float*)(smem + S_B2);

    const int lane = tid & 31;
    const int wid  = tid >> 5;
    const int gw   = blockIdx.x * WARPS + wid;
    const int gstride = gridDim.x * WARPS;

    // per-thread fixed fragment coordinates
    const int qrow = lane >> 2;        // 0..7
    const int qcol = (lane & 3) * 2;   // 0,2,4,6

    for (int g = gw; g < ngroups; g += gstride) {
        const int r0 = g * 16 + qrow;
        const int r1 = r0 + 8;
        const int gb0 = batch[r0];
        const int gb1 = batch[r1];

        float acc[64];   // GEMM1 C: 16 n-tiles x 4
        #pragma unroll
        for (int i = 0; i < 64; ++i) acc[i] = 0.f;

        // ================= GEMM1: K = 384 in 24 k16-tiles =================
        #pragma unroll 1
        for (int kt = 0; kt < KT1; ++kt) {
            const int col0 = kt * 16 + qcol;
            const float *p0, *p1;
            if (kt < 4)       { p0 = ek  + (size_t)r0 * NEF + col0;         p1 = ek  + (size_t)r1 * NEF + col0; }
            else if (kt < 12) { p0 = vrk + (size_t)r0 * NNF + (col0 - 64);  p1 = vrk + (size_t)r1 * NNF + (col0 - 64); }
            else if (kt < 20) { p0 = vsk + (size_t)r0 * NNF + (col0 - 192); p1 = vsk + (size_t)r1 * NNF + (col0 - 192); }
            else              { p0 = u + (size_t)gb0 * NGF + (col0 - 320);  p1 = u + (size_t)gb1 * NGF + (col0 - 320); }

            const float2 v0 = *(const float2*)p0;         // (r0, col0..col0+1)
            const float2 v1 = *(const float2*)p1;         // (r1, ...)
            const float2 v2 = *(const float2*)(p0 + 8);   // (r0, col0+8..)
            const float2 v3 = *(const float2*)(p1 + 8);   // (r1, col0+8..)

            uint32_t ah[4], al[4];
            split2(v0, ah[0], al[0]);
            split2(v1, ah[1], al[1]);
            split2(v2, ah[2], al[2]);
            split2(v3, ah[3], al[3]);

            const uint2* bh = w1h + (size_t)kt * NT1 * 32 + lane;
            const uint2* bl = w1l + (size_t)kt * NT1 * 32 + lane;
            #pragma unroll
            for (int nt = 0; nt < NT1; ++nt) {
                const uint2 fh = bh[nt * 32];
                const uint2 fl = bl[nt * 32];
                mma_bf16(acc + nt * 4, ah, fh.x, fh.y);   // xh * Wh
                mma_bf16(acc + nt * 4, ah, fl.x, fl.y);   // xh * Wl
                mma_bf16(acc + nt * 4, al, fh.x, fh.y);   // xl * Wh
            }
        }

        // ================= bias + ReLU =================
        #pragma unroll
        for (int nt = 0; nt < NT1; ++nt) {
            const float2 bb = *(const float2*)(b1s + nt * 8 + qcol);
            acc[nt * 4 + 0] = fmaxf(acc[nt * 4 + 0] + bb.x, 0.f);
            acc[nt * 4 + 1] = fmaxf(acc[nt * 4 + 1] + bb.y, 0.f);
            acc[nt * 4 + 2] = fmaxf(acc[nt * 4 + 2] + bb.x, 0.f);
            acc[nt * 4 + 3] = fmaxf(acc[nt * 4 + 3] + bb.y, 0.f);
        }

        // ================= GEMM2: h [16x128] @ W2 [128x64], register A =================
        float c2[32];   // 8 n-tiles x 4
        #pragma unroll
        for (int i = 0; i < 32; ++i) c2[i] = 0.f;

        #pragma unroll
        for (int kt = 0; kt < KT2; ++kt) {
            // A fragment for k-cols 16kt..16kt+15 == C1 n-tiles 2kt, 2kt+1 (layout identity)
            const float* s0 = acc + kt * 8;
            float h0 = bhi(s0[0]), h1 = bhi(s0[1]), h2 = bhi(s0[2]), h3 = bhi(s0[3]);
            float h4 = bhi(s0[4]), h5 = bhi(s0[5]), h6 = bhi(s0[6]), h7 = bhi(s0[7]);
            uint32_t ah[4], al[4];
            ah[0] = pack2(h0, h1); ah[1] = pack2(h2, h3);
            ah[2] = pack2(h4, h5); ah[3] = pack2(h6, h7);
            al[0] = pack2(s0[0] - h0, s0[1] - h1); al[1] = pack2(s0[2] - h2, s0[3] - h3);
            al[2] = pack2(s0[4] - h4, s0[5] - h5); al[3] = pack2(s0[6] - h6, s0[7] - h7);

            const uint2* bh = w2h + (size_t)kt * NT2 * 32 + lane;
            const uint2* bl = w2l + (size_t)kt * NT2 * 32 + lane;
            #pragma unroll
            for (int nt = 0; nt < NT2; ++nt) {
                const uint2 fh = bh[nt * 32];
                const uint2 fl = bl[nt * 32];
                mma_bf16(c2 + nt * 4, ah, fh.x, fh.y);
                mma_bf16(c2 + nt * 4, ah, fl.x, fl.y);
                mma_bf16(c2 + nt * 4, al, fh.x, fh.y);
            }
        }

        // ================= epilogue: + b2, store fp32 =================
        #pragma unroll
        for (int nt = 0; nt < NT2; ++nt) {
            const float2 bb = *(const float2*)(b2s + nt * 8 + qcol);
            float2 o0, o1;
            o0.x = c2[nt * 4 + 0] + bb.x;
            o0.y = c2[nt * 4 + 1] + bb.y;
            o1.x = c2[nt * 4 + 2] + bb.x;
            o1.y = c2[nt * 4 + 3] + bb.y;
            *(float2*)(out + (size_t)r0 * TGT + nt * 8 + qcol) = o0;
            *(float2*)(out + (size_t)r1 * TGT + nt * 8 + qcol) = o1;
        }
    }
}

// ===================== launch =====================
extern "C" void kernel_launch(void* const* d_in, const int* in_sizes, int n_in,
                              void* d_out, int out_size) {
    (void)n_in; (void)out_size;
    const float* ek  = (const float*)d_in[0];
    const float* vrk = (const float*)d_in[1];
    const float* vsk = (const float*)d_in[2];
    const float* u   = (const float*)d_in[3];
    const int*   batch = (const int*)d_in[4];   // int32 (jax default x64 disabled)
    const float* W1  = (const float*)d_in[5];
    const float* b1  = (const float*)d_in[6];
    const float* W2  = (const float*)d_in[7];
    const float* b2  = (const float*)d_in[8];
    float* out = (float*)d_out;

    const int E = in_sizes[0] / NEF;
    const int ngroups = E / 16;

    const int prep_total = KT1 * NT1 * 32 + KT2 * NT2 * 32;
    prep_kernel<<<(prep_total + 255) / 256, 256>>>(W1, W2);

    cudaFuncSetAttribute(edge_mlp, cudaFuncAttributeMaxDynamicSharedMemorySize, S_TOTAL);
    edge_mlp<<<GRID_X, THREADS, S_TOTAL>>>(ek, vrk, vsk, u, batch, b1, b2, out, ngroups);
}

// round 5
// speedup vs baseline: 1.5763x; 1.5763x over previous
#include <cuda_runtime.h>
#include <cuda_fp16.h>
#include <cstdint>

// ===================== problem constants =====================
#define NNF 128
#define NEF 64
#define NGF 64
#define HID 128
#define TGT 64

#define THREADS 512
#define WARPS 16
#define GRID_X 152

// fragment tile counts
#define KT1 24   // 384/16 k-tiles, GEMM1
#define NT1 16   // 128/8  n-tiles, GEMM1
#define KT2 8    // 128/16 k-tiles, GEMM2
#define NT2 8    // 64/8   n-tiles, GEMM2

// ===================== smem offsets (bytes) =====================
#define S_W1  0u        // 24*16*32*8 = 98304 (fp16 W1 fragments)
#define S_W2  98304u    // 8*8*32*8  = 16384
#define S_B1  114688u   // 512
#define S_B2  115200u   // 256
#define S_TOTAL 115456u

// ===================== helpers =====================
__device__ __forceinline__ uint32_t pack2h(float lo, float hi) {
    // f16x2 with 'lo' in low 16 bits (first PTX source -> high half)
    uint32_t r;
    asm("cvt.rn.f16x2.f32 %0, %1, %2;" : "=r"(r) : "f"(hi), "f"(lo));
    return r;
}
__device__ __forceinline__ float hrnd(float x) {
    return __half2float(__float2half_rn(x));
}
__device__ __forceinline__ void split2h(float2 v, uint32_t& hi, uint32_t& lo) {
    float hx = hrnd(v.x), hy = hrnd(v.y);
    hi = pack2h(hx, hy);
    lo = pack2h(v.x - hx, v.y - hy);
}
// D += A * B  (m16n8k16, fp16 in, f32 accum)
__device__ __forceinline__ void mma_f16(float* c, const uint32_t* a, uint32_t b0, uint32_t b1) {
    asm volatile("mma.sync.aligned.m16n8k16.row.col.f32.f16.f16.f32 "
        "{%0,%1,%2,%3}, {%4,%5,%6,%7}, {%8,%9}, {%0,%1,%2,%3};"
        : "+f"(c[0]), "+f"(c[1]), "+f"(c[2]), "+f"(c[3])
        : "r"(a[0]), "r"(a[1]), "r"(a[2]), "r"(a[3]), "r"(b0), "r"(b1));
}

// ===================== device scratch =====================
__device__ __align__(16) uint2 g_w1[KT1 * NT1 * 32];
__device__ __align__(16) uint2 g_w2[KT2 * NT2 * 32];
__device__ unsigned int g_counter;

// Pack W1 [384,128] and W2 [128,64] ([k][n] row-major) into per-lane m16n8k16
// B fragments (fp16): entry ((kt*NT+nt)*32+lane):
//   .x = {W[k0][n], W[k0+1][n]}, .y = {W[k0+8][n], W[k0+9][n]},
//   k0 = kt*16 + (lane&3)*2, n = nt*8 + (lane>>2).
__global__ void prep_kernel(const float* __restrict__ W1, const float* __restrict__ W2) {
    int idx = blockIdx.x * blockDim.x + threadIdx.x;
    if (idx == 0) g_counter = 0u;
    const int total1 = KT1 * NT1 * 32;
    if (idx < total1) {
        int lane = idx & 31, tile = idx >> 5;
        int nt = tile % NT1, kt = tile / NT1;
        int k0 = kt * 16 + (lane & 3) * 2;
        int n  = nt * 8 + (lane >> 2);
        float w00 = W1[(size_t)k0 * HID + n];
        float w01 = W1[(size_t)(k0 + 1) * HID + n];
        float w10 = W1[(size_t)(k0 + 8) * HID + n];
        float w11 = W1[(size_t)(k0 + 9) * HID + n];
        g_w1[idx] = make_uint2(pack2h(w00, w01), pack2h(w10, w11));
    } else if (idx < total1 + KT2 * NT2 * 32) {
        int j = idx - total1;
        int lane = j & 31, tile = j >> 5;
        int nt = tile % NT2, kt = tile / NT2;
        int k0 = kt * 16 + (lane & 3) * 2;
        int n  = nt * 8 + (lane >> 2);
        float w00 = W2[(size_t)k0 * TGT + n];
        float w01 = W2[(size_t)(k0 + 1) * TGT + n];
        float w10 = W2[(size_t)(k0 + 8) * TGT + n];
        float w11 = W2[(size_t)(k0 + 9) * TGT + n];
        g_w2[j] = make_uint2(pack2h(w00, w01), pack2h(w10, w11));
    }
}

// ===================== main fused kernel =====================
extern "C" __global__ void __launch_bounds__(THREADS, 1)
edge_mlp(const float* __restrict__ ek, const float* __restrict__ vrk,
         const float* __restrict__ vsk, const float* __restrict__ u,
         const int* __restrict__ batch,
         const float* __restrict__ b1, const float* __restrict__ b2,
         float* __restrict__ out, int ngroups) {
    extern __shared__ __align__(16) unsigned char smem[];
    const int tid = threadIdx.x;

    // -------- prologue: weight fragments + biases to smem --------
    {
        uint4* d = (uint4*)(smem + S_W1);
        const uint4* s = (const uint4*)g_w1;
        for (int i = tid; i < 98304 / 16; i += THREADS) d[i] = s[i];
        d = (uint4*)(smem + S_W2); s = (const uint4*)g_w2;
        for (int i = tid; i < 16384 / 16; i += THREADS) d[i] = s[i];
        float* b1s = (float*)(smem + S_B1);
        float* b2s = (float*)(smem + S_B2);
        if (tid < HID) b1s[tid] = b1[tid];
        if (tid < TGT) b2s[tid] = b2[tid];
    }
    __syncthreads();

    const uint2* w1 = (const uint2*)(smem + S_W1);
    const uint2* w2 = (const uint2*)(smem + S_W2);
    const float* b1s = (const float*)(smem + S_B1);
    const float* b2s = (const float*)(smem + S_B2);

    const int lane = tid & 31;
    const int qrow = lane >> 2;        // 0..7
    const int qcol = (lane & 3) * 2;   // 0,2,4,6

    // dynamic work stealing
    unsigned int cur = 0xFFFFFFFFu;
    if (lane == 0) cur = atomicAdd(&g_counter, 1u);
    cur = __shfl_sync(0xFFFFFFFFu, cur, 0);

    while (cur < (unsigned)ngroups) {
        unsigned int nxt = 0xFFFFFFFFu;
        if (lane == 0) nxt = atomicAdd(&g_counter, 1u);   // issued early, latency hidden

        const int r0 = (int)cur * 16 + qrow;
        const int r1 = r0 + 8;
        const int gb0 = batch[r0];
        const int gb1 = batch[r1];

        float acc[64];   // GEMM1 C: 16 n-tiles x 4
        #pragma unroll
        for (int i = 0; i < 64; ++i) acc[i] = 0.f;

        // ================= GEMM1: K = 384 in 24 k16-tiles, pipelined loads =================
        float2 v0, v1, v2, v3;
        {
            const float* p0 = ek + (size_t)r0 * NEF + qcol;
            const float* p1 = ek + (size_t)r1 * NEF + qcol;
            v0 = *(const float2*)p0;       v1 = *(const float2*)p1;
            v2 = *(const float2*)(p0 + 8); v3 = *(const float2*)(p1 + 8);
        }
        #pragma unroll 1
        for (int kt = 0; kt < KT1; ++kt) {
            // ---- prefetch kt+1 ----
            float2 n0, n1, n2, n3;
            {
                const int kn = (kt + 1 < KT1) ? kt + 1 : KT1 - 1;
                const int c0 = kn * 16 + qcol;
                const float *p0, *p1;
                if (kn < 4)       { p0 = ek  + (size_t)r0 * NEF + c0;          p1 = ek  + (size_t)r1 * NEF + c0; }
                else if (kn < 12) { p0 = vrk + (size_t)r0 * NNF + (c0 - 64);   p1 = vrk + (size_t)r1 * NNF + (c0 - 64); }
                else if (kn < 20) { p0 = vsk + (size_t)r0 * NNF + (c0 - 192);  p1 = vsk + (size_t)r1 * NNF + (c0 - 192); }
                else              { p0 = u + (size_t)gb0 * NGF + (c0 - 320);   p1 = u + (size_t)gb1 * NGF + (c0 - 320); }
                n0 = *(const float2*)p0;       n1 = *(const float2*)p1;
                n2 = *(const float2*)(p0 + 8); n3 = *(const float2*)(p1 + 8);
            }

            // ---- A fragments: x split into fp16 hi + lo ----
            uint32_t ah[4], al[4];
            split2h(v0, ah[0], al[0]);
            split2h(v1, ah[1], al[1]);
            split2h(v2, ah[2], al[2]);
            split2h(v3, ah[3], al[3]);

            const uint2* bw = w1 + (size_t)kt * NT1 * 32 + lane;
            #pragma unroll
            for (int nt = 0; nt < NT1; ++nt) {
                const uint2 f = bw[nt * 32];
                mma_f16(acc + nt * 4, ah, f.x, f.y);   // xh * W
                mma_f16(acc + nt * 4, al, f.x, f.y);   // xl * W
            }

            v0 = n0; v1 = n1; v2 = n2; v3 = n3;
        }

        // ================= bias + ReLU =================
        #pragma unroll
        for (int nt = 0; nt < NT1; ++nt) {
            const float2 bb = *(const float2*)(b1s + nt * 8 + qcol);
            acc[nt * 4 + 0] = fmaxf(acc[nt * 4 + 0] + bb.x, 0.f);
            acc[nt * 4 + 1] = fmaxf(acc[nt * 4 + 1] + bb.y, 0.f);
            acc[nt * 4 + 2] = fmaxf(acc[nt * 4 + 2] + bb.x, 0.f);
            acc[nt * 4 + 3] = fmaxf(acc[nt * 4 + 3] + bb.y, 0.f);
        }

        // ================= GEMM2: h [16x128] @ W2 [128x64], register A =================
        float c2[32];
        #pragma unroll
        for (int i = 0; i < 32; ++i) c2[i] = 0.f;

        #pragma unroll
        for (int kt = 0; kt < KT2; ++kt) {
            // C1 fragment (n-tiles 2kt,2kt+1) == A2 fragment for k-cols 16kt..16kt+15
            const float* s0 = acc + kt * 8;
            float h0 = hrnd(s0[0]), h1 = hrnd(s0[1]), h2 = hrnd(s0[2]), h3 = hrnd(s0[3]);
            float h4 = hrnd(s0[4]), h5 = hrnd(s0[5]), h6 = hrnd(s0[6]), h7 = hrnd(s0[7]);
            uint32_t ah[4], al[4];
            ah[0] = pack2h(h0, h1); ah[1] = pack2h(h2, h3);
            ah[2] = pack2h(h4, h5); ah[3] = pack2h(h6, h7);
            al[0] = pack2h(s0[0] - h0, s0[1] - h1); al[1] = pack2h(s0[2] - h2, s0[3] - h3);
            al[2] = pack2h(s0[4] - h4, s0[5] - h5); al[3] = pack2h(s0[6] - h6, s0[7] - h7);

            const uint2* bw = w2 + (size_t)kt * NT2 * 32 + lane;
            #pragma unroll
            for (int nt = 0; nt < NT2; ++nt) {
                const uint2 f = bw[nt * 32];
                mma_f16(c2 + nt * 4, ah, f.x, f.y);
                mma_f16(c2 + nt * 4, al, f.x, f.y);
            }
        }

        // ================= epilogue: + b2, store fp32 =================
        #pragma unroll
        for (int nt = 0; nt < NT2; ++nt) {
            const float2 bb = *(const float2*)(b2s + nt * 8 + qcol);
            float2 o0, o1;
            o0.x = c2[nt * 4 + 0] + bb.x;
            o0.y = c2[nt * 4 + 1] + bb.y;
            o1.x = c2[nt * 4 + 2] + bb.x;
            o1.y = c2[nt * 4 + 3] + bb.y;
            *(float2*)(out + (size_t)r0 * TGT + nt * 8 + qcol) = o0;
            *(float2*)(out + (size_t)r1 * TGT + nt * 8 + qcol) = o1;
        }

        cur = __shfl_sync(0xFFFFFFFFu, nxt, 0);
    }
}

// ===================== launch =====================
extern "C" void kernel_launch(void* const* d_in, const int* in_sizes, int n_in,
                              void* d_out, int out_size) {
    (void)n_in; (void)out_size;
    const float* ek  = (const float*)d_in[0];
    const float* vrk = (const float*)d_in[1];
    const float* vsk = (const float*)d_in[2];
    const float* u   = (const float*)d_in[3];
    const int*   batch = (const int*)d_in[4];
    const float* W1  = (const float*)d_in[5];
    const float* b1  = (const float*)d_in[6];
    const float* W2  = (const float*)d_in[7];
    const float* b2  = (const float*)d_in[8];
    float* out = (float*)d_out;

    const int E = in_sizes[0] / NEF;
    const int ngroups = E / 16;

    const int prep_total = KT1 * NT1 * 32 + KT2 * NT2 * 32;
    prep_kernel<<<(prep_total + 255) / 256, 256>>>(W1, W2);

    cudaFuncSetAttribute(edge_mlp, cudaFuncAttributeMaxDynamicSharedMemorySize, S_TOTAL);
    edge_mlp<<<GRID_X, THREADS, S_TOTAL>>>(ek, vrk, vsk, u, batch, b1, b2, out, ngroups);
}

// round 6
// speedup vs baseline: 2.1549x; 1.3670x over previous
#include <cuda_runtime.h>
#include <cuda_fp16.h>
#include <cstdint>

// ===================== problem constants =====================
#define NNF 128
#define NEF 64
#define NGF 64
#define HID 128
#define TGT 64

#define THREADS 512
#define WARPS 16
#define GRID_X 152

// fragment tile counts
#define KT1 24   // 384/16 k-tiles, GEMM1
#define NT1 16   // 128/8  n-tiles, GEMM1
#define KT2 8    // 128/16 k-tiles, GEMM2
#define NT2 8    // 64/8   n-tiles, GEMM2

// ===================== smem offsets (bytes) =====================
#define S_W1  0u        // 24*16*32*8 = 98304 (fp16 W1 fragments)
#define S_W2  98304u    // 8*8*32*8  = 16384
#define S_B1  114688u   // 512
#define S_B2  115200u   // 256
#define S_TOTAL 115456u

// ===================== helpers =====================
__device__ __forceinline__ uint32_t pack2h(float lo, float hi) {
    // f16x2 with 'lo' in low 16 bits (first PTX source -> high half)
    uint32_t r;
    asm("cvt.rn.f16x2.f32 %0, %1, %2;" : "=r"(r) : "f"(hi), "f"(lo));
    return r;
}
// D += A * B  (m16n8k16, fp16 in, f32 accum)
__device__ __forceinline__ void mma_f16(float* c, const uint32_t* a, uint32_t b0, uint32_t b1) {
    asm volatile("mma.sync.aligned.m16n8k16.row.col.f32.f16.f16.f32 "
        "{%0,%1,%2,%3}, {%4,%5,%6,%7}, {%8,%9}, {%0,%1,%2,%3};"
        : "+f"(c[0]), "+f"(c[1]), "+f"(c[2]), "+f"(c[3])
        : "r"(a[0]), "r"(a[1]), "r"(a[2]), "r"(a[3]), "r"(b0), "r"(b1));
}

// ===================== device scratch =====================
__device__ __align__(16) uint2 g_w1[KT1 * NT1 * 32];
__device__ __align__(16) uint2 g_w2[KT2 * NT2 * 32];
__device__ unsigned int g_counter;

// Pack W1 [384,128] and W2 [128,64] ([k][n] row-major) into per-lane m16n8k16
// B fragments (fp16): entry ((kt*NT+nt)*32+lane):
//   .x = {W[k0][n], W[k0+1][n]}, .y = {W[k0+8][n], W[k0+9][n]},
//   k0 = kt*16 + (lane&3)*2, n = nt*8 + (lane>>2).
__global__ void prep_kernel(const float* __restrict__ W1, const float* __restrict__ W2) {
    int idx = blockIdx.x * blockDim.x + threadIdx.x;
    if (idx == 0) g_counter = 0u;
    const int total1 = KT1 * NT1 * 32;
    if (idx < total1) {
        int lane = idx & 31, tile = idx >> 5;
        int nt = tile % NT1, kt = tile / NT1;
        int k0 = kt * 16 + (lane & 3) * 2;
        int n  = nt * 8 + (lane >> 2);
        float w00 = W1[(size_t)k0 * HID + n];
        float w01 = W1[(size_t)(k0 + 1) * HID + n];
        float w10 = W1[(size_t)(k0 + 8) * HID + n];
        float w11 = W1[(size_t)(k0 + 9) * HID + n];
        g_w1[idx] = make_uint2(pack2h(w00, w01), pack2h(w10, w11));
    } else if (idx < total1 + KT2 * NT2 * 32) {
        int j = idx - total1;
        int lane = j & 31, tile = j >> 5;
        int nt = tile % NT2, kt = tile / NT2;
        int k0 = kt * 16 + (lane & 3) * 2;
        int n  = nt * 8 + (lane >> 2);
        float w00 = W2[(size_t)k0 * TGT + n];
        float w01 = W2[(size_t)(k0 + 1) * TGT + n];
        float w10 = W2[(size_t)(k0 + 8) * TGT + n];
        float w11 = W2[(size_t)(k0 + 9) * TGT + n];
        g_w2[j] = make_uint2(pack2h(w00, w01), pack2h(w10, w11));
    }
}

// ===================== main fused kernel =====================
extern "C" __global__ void __launch_bounds__(THREADS, 1)
edge_mlp(const float* __restrict__ ek, const float* __restrict__ vrk,
         const float* __restrict__ vsk, const float* __restrict__ u,
         const int* __restrict__ batch,
         const float* __restrict__ b1, const float* __restrict__ b2,
         float* __restrict__ out, int ngroups) {
    extern __shared__ __align__(16) unsigned char smem[];
    const int tid = threadIdx.x;

    // -------- prologue: weight fragments + biases to smem --------
    {
        uint4* d = (uint4*)(smem + S_W1);
        const uint4* s = (const uint4*)g_w1;
        for (int i = tid; i < 98304 / 16; i += THREADS) d[i] = s[i];
        d = (uint4*)(smem + S_W2); s = (const uint4*)g_w2;
        for (int i = tid; i < 16384 / 16; i += THREADS) d[i] = s[i];
        float* b1s = (float*)(smem + S_B1);
        float* b2s = (float*)(smem + S_B2);
        if (tid < HID) b1s[tid] = b1[tid];
        if (tid < TGT) b2s[tid] = b2[tid];
    }
    __syncthreads();

    const uint2* w1 = (const uint2*)(smem + S_W1);
    const uint2* w2 = (const uint2*)(smem + S_W2);
    const float* b1s = (const float*)(smem + S_B1);
    const float* b2s = (const float*)(smem + S_B2);

    const int lane = tid & 31;
    const int qrow = lane >> 2;        // 0..7
    const int qcol = (lane & 3) * 2;   // 0,2,4,6

    // dynamic work stealing
    unsigned int cur = 0xFFFFFFFFu;
    if (lane == 0) cur = atomicAdd(&g_counter, 1u);
    cur = __shfl_sync(0xFFFFFFFFu, cur, 0);

    while (cur < (unsigned)ngroups) {
        unsigned int nxt = 0xFFFFFFFFu;
        if (lane == 0) nxt = atomicAdd(&g_counter, 1u);   // issued early, latency hidden

        const int r0 = (int)cur * 16 + qrow;
        const int r1 = r0 + 8;
        const int gb0 = batch[r0];
        const int gb1 = batch[r1];

        float acc[64];   // GEMM1 C: 16 n-tiles x 4
        #pragma unroll
        for (int i = 0; i < 64; ++i) acc[i] = 0.f;

        // ================= GEMM1: K = 384 in 24 k16-tiles, pipelined loads =================
        float2 v0, v1, v2, v3;
        {
            const float* p0 = ek + (size_t)r0 * NEF + qcol;
            const float* p1 = ek + (size_t)r1 * NEF + qcol;
            v0 = *(const float2*)p0;       v1 = *(const float2*)p1;
            v2 = *(const float2*)(p0 + 8); v3 = *(const float2*)(p1 + 8);
        }
        #pragma unroll 1
        for (int kt = 0; kt < KT1; ++kt) {
            // ---- prefetch kt+1 ----
            float2 n0, n1, n2, n3;
            {
                const int kn = (kt + 1 < KT1) ? kt + 1 : KT1 - 1;
                const int c0 = kn * 16 + qcol;
                const float *p0, *p1;
                if (kn < 4)       { p0 = ek  + (size_t)r0 * NEF + c0;          p1 = ek  + (size_t)r1 * NEF + c0; }
                else if (kn < 12) { p0 = vrk + (size_t)r0 * NNF + (c0 - 64);   p1 = vrk + (size_t)r1 * NNF + (c0 - 64); }
                else if (kn < 20) { p0 = vsk + (size_t)r0 * NNF + (c0 - 192);  p1 = vsk + (size_t)r1 * NNF + (c0 - 192); }
                else              { p0 = u + (size_t)gb0 * NGF + (c0 - 320);   p1 = u + (size_t)gb1 * NGF + (c0 - 320); }
                n0 = *(const float2*)p0;       n1 = *(const float2*)p1;
                n2 = *(const float2*)(p0 + 8); n3 = *(const float2*)(p1 + 8);
            }

            // ---- A fragments: single fp16 (error budget allows; see analysis) ----
            uint32_t a[4];
            a[0] = pack2h(v0.x, v0.y);
            a[1] = pack2h(v1.x, v1.y);
            a[2] = pack2h(v2.x, v2.y);
            a[3] = pack2h(v3.x, v3.y);

            const uint2* bw = w1 + (size_t)kt * NT1 * 32 + lane;
            #pragma unroll
            for (int nt = 0; nt < NT1; ++nt) {
                const uint2 f = bw[nt * 32];
                mma_f16(acc + nt * 4, a, f.x, f.y);
            }

            v0 = n0; v1 = n1; v2 = n2; v3 = n3;
        }

        // ================= bias + ReLU =================
        #pragma unroll
        for (int nt = 0; nt < NT1; ++nt) {
            const float2 bb = *(const float2*)(b1s + nt * 8 + qcol);
            acc[nt * 4 + 0] = fmaxf(acc[nt * 4 + 0] + bb.x, 0.f);
            acc[nt * 4 + 1] = fmaxf(acc[nt * 4 + 1] + bb.y, 0.f);
            acc[nt * 4 + 2] = fmaxf(acc[nt * 4 + 2] + bb.x, 0.f);
            acc[nt * 4 + 3] = fmaxf(acc[nt * 4 + 3] + bb.y, 0.f);
        }

        // ================= GEMM2: h [16x128] @ W2 [128x64], register A =================
        float c2[32];
        #pragma unroll
        for (int i = 0; i < 32; ++i) c2[i] = 0.f;

        #pragma unroll
        for (int kt = 0; kt < KT2; ++kt) {
            // C1 fragment (n-tiles 2kt,2kt+1) == A2 fragment for k-cols 16kt..16kt+15
            const float* s0 = acc + kt * 8;
            uint32_t a[4];
            a[0] = pack2h(s0[0], s0[1]); a[1] = pack2h(s0[2], s0[3]);
            a[2] = pack2h(s0[4], s0[5]); a[3] = pack2h(s0[6], s0[7]);

            const uint2* bw = w2 + (size_t)kt * NT2 * 32 + lane;
            #pragma unroll
            for (int nt = 0; nt < NT2; ++nt) {
                const uint2 f = bw[nt * 32];
                mma_f16(c2 + nt * 4, a, f.x, f.y);
            }
        }

        // ================= epilogue: + b2, store fp32 =================
        #pragma unroll
        for (int nt = 0; nt < NT2; ++nt) {
            const float2 bb = *(const float2*)(b2s + nt * 8 + qcol);
            float2 o0, o1;
            o0.x = c2[nt * 4 + 0] + bb.x;
            o0.y = c2[nt * 4 + 1] + bb.y;
            o1.x = c2[nt * 4 + 2] + bb.x;
            o1.y = c2[nt * 4 + 3] + bb.y;
            *(float2*)(out + (size_t)r0 * TGT + nt * 8 + qcol) = o0;
            *(float2*)(out + (size_t)r1 * TGT + nt * 8 + qcol) = o1;
        }

        cur = __shfl_sync(0xFFFFFFFFu, nxt, 0);
    }
}

// ===================== launch =====================
extern "C" void kernel_launch(void* const* d_in, const int* in_sizes, int n_in,
                              void* d_out, int out_size) {
    (void)n_in; (void)out_size;
    const float* ek  = (const float*)d_in[0];
    const float* vrk = (const float*)d_in[1];
    const float* vsk = (const float*)d_in[2];
    const float* u   = (const float*)d_in[3];
    const int*   batch = (const int*)d_in[4];
    const float* W1  = (const float*)d_in[5];
    const float* b1  = (const float*)d_in[6];
    const float* W2  = (const float*)d_in[7];
    const float* b2  = (const float*)d_in[8];
    float* out = (float*)d_out;

    const int E = in_sizes[0] / NEF;
    const int ngroups = E / 16;

    const int prep_total = KT1 * NT1 * 32 + KT2 * NT2 * 32;
    prep_kernel<<<(prep_total + 255) / 256, 256>>>(W1, W2);

    cudaFuncSetAttribute(edge_mlp, cudaFuncAttributeMaxDynamicSharedMemorySize, S_TOTAL);
    edge_mlp<<<GRID_X, THREADS, S_TOTAL>>>(ek, vrk, vsk, u, batch, b1, b2, out, ngroups);
}